// round 1
// baseline (speedup 1.0000x reference)
#include <cuda_runtime.h>
#include <cuda_bf16.h>
#include <cstdint>

typedef unsigned long long ull;

#define MAXN 100000
#define MAXE 3200000
#define D 256

// ---------------- scratch (static __device__ globals: allowed) ----------------
__device__ float g_side[(size_t)MAXN * D];   // SpMM result
__device__ float g_sval[MAXE];               // edge vals sorted by row
__device__ int   g_scol[MAXE];               // edge cols sorted by row
__device__ int   g_hist[MAXN];
__device__ int   g_off[MAXN + 1];
__device__ int   g_cur[MAXN];

// ---------------- small helpers ----------------
__device__ __forceinline__ ull pack2(float lo, float hi) {
    ull r; asm("mov.b64 %0, {%1, %2};" : "=l"(r) : "f"(lo), "f"(hi)); return r;
}
__device__ __forceinline__ void unpack2(ull v, float& lo, float& hi) {
    asm("mov.b64 {%0, %1}, %2;" : "=f"(lo), "=f"(hi) : "l"(v));
}
// packed dual FMA: d.lo += a.lo*b.lo ; d.hi += a.hi*b.hi
__device__ __forceinline__ void ffma2(ull& d, ull a, ull b) {
    asm("fma.rn.f32x2 %0, %1, %2, %0;" : "+l"(d) : "l"(a), "l"(b));
}
__device__ __forceinline__ float lrelu(float x) { return x > 0.0f ? x : 0.01f * x; }

// ---------------- 1. zero histogram ----------------
__global__ void zero_hist_kernel(int n) {
    int i = blockIdx.x * blockDim.x + threadIdx.x;
    if (i < n) g_hist[i] = 0;
}

// ---------------- 2. histogram of edge rows ----------------
__global__ void hist_kernel(const int* __restrict__ rows, int e) {
    int i = blockIdx.x * blockDim.x + threadIdx.x;
    if (i < e) atomicAdd(&g_hist[rows[i]], 1);
}

// ---------------- 3. exclusive scan (single block) ----------------
__global__ void scan_kernel(int n) {
    __shared__ int wsum[32];
    __shared__ int carry_s;
    int t = threadIdx.x, lane = t & 31, w = t >> 5;
    if (t == 0) { carry_s = 0; g_off[0] = 0; }
    __syncthreads();
    for (int base = 0; base < n; base += 1024) {
        int i = base + t;
        int v = (i < n) ? g_hist[i] : 0;
        int x = v;
        #pragma unroll
        for (int d2 = 1; d2 < 32; d2 <<= 1) {
            int y = __shfl_up_sync(0xffffffffu, x, d2);
            if (lane >= d2) x += y;
        }
        if (lane == 31) wsum[w] = x;
        __syncthreads();
        if (w == 0) {
            int s = wsum[lane];
            #pragma unroll
            for (int d2 = 1; d2 < 32; d2 <<= 1) {
                int y = __shfl_up_sync(0xffffffffu, s, d2);
                if (lane >= d2) s += y;
            }
            wsum[lane] = s;
        }
        __syncthreads();
        int incl = x + (w > 0 ? wsum[w - 1] : 0);
        int carry = carry_s;
        if (i < n) {
            g_off[i + 1] = carry + incl;
            g_cur[i]     = carry + incl - v;   // exclusive prefix = scatter cursor
        }
        int total = wsum[31];
        __syncthreads();
        if (t == 0) carry_s = carry + total;
        __syncthreads();
    }
}

// ---------------- 4. scatter edges to CSR order ----------------
__global__ void scatter_kernel(const int* __restrict__ rows, const int* __restrict__ cols,
                               const float* __restrict__ vals, int e) {
    int i = blockIdx.x * blockDim.x + threadIdx.x;
    if (i < e) {
        int r = rows[i];
        int p = atomicAdd(&g_cur[r], 1);
        g_scol[p] = cols[i];
        g_sval[p] = vals[i];
    }
}

// ---------------- 5. CSR SpMM: one block (64 threads) per node ----------------
__global__ __launch_bounds__(64) void spmm_kernel(const float4* __restrict__ ego4) {
    int node = blockIdx.x;
    int t = threadIdx.x;               // thread owns 4 consecutive dims (float4)
    int beg = g_off[node], end = g_off[node + 1];
    float4 a0 = {0,0,0,0}, a1 = a0, a2 = a0, a3 = a0;
    int e = beg;
    for (; e + 4 <= end; e += 4) {
        int   c0 = g_scol[e],   c1 = g_scol[e+1], c2 = g_scol[e+2], c3 = g_scol[e+3];
        float v0 = g_sval[e],   v1 = g_sval[e+1], v2 = g_sval[e+2], v3 = g_sval[e+3];
        float4 x0 = ego4[(size_t)c0 * 64 + t];
        float4 x1 = ego4[(size_t)c1 * 64 + t];
        float4 x2 = ego4[(size_t)c2 * 64 + t];
        float4 x3 = ego4[(size_t)c3 * 64 + t];
        a0.x += v0*x0.x; a0.y += v0*x0.y; a0.z += v0*x0.z; a0.w += v0*x0.w;
        a1.x += v1*x1.x; a1.y += v1*x1.y; a1.z += v1*x1.z; a1.w += v1*x1.w;
        a2.x += v2*x2.x; a2.y += v2*x2.y; a2.z += v2*x2.z; a2.w += v2*x2.w;
        a3.x += v3*x3.x; a3.y += v3*x3.y; a3.z += v3*x3.z; a3.w += v3*x3.w;
    }
    for (; e < end; e++) {
        int c = g_scol[e]; float v = g_sval[e];
        float4 x = ego4[(size_t)c * 64 + t];
        a0.x += v*x.x; a0.y += v*x.y; a0.z += v*x.z; a0.w += v*x.w;
    }
    float4 r;
    r.x = (a0.x + a1.x) + (a2.x + a3.x);
    r.y = (a0.y + a1.y) + (a2.y + a3.y);
    r.z = (a0.z + a1.z) + (a2.z + a3.z);
    r.w = (a0.w + a1.w) + (a2.w + a3.w);
    ((float4*)g_side)[(size_t)node * 64 + t] = r;
}

// ---------------- 6. fused dual GEMM + bias + leaky_relu + add ----------------
// out[m][j] = lrelu( sum_k (ego+side)[m][k] * W1[j][k] + b1[j] )
//           + lrelu( sum_k (ego*side)[m][k] * W2[j][k] + b2[j] )
#define BM 128
#define BN 128
#define BK 16
#define SSTR 129   // ull stride per k-row of Sdup/Pdup
#define WSTR 130   // float stride per k-row of W tiles (conflict-free STS)
#define GEMM_SMEM (2*BK*SSTR*8 + 2*BK*WSTR*4)   // 33024 + 16640 = 49664 B

__global__ __launch_bounds__(256, 1) void gemm_kernel(
    const float* __restrict__ ego,
    const float* __restrict__ W1, const float* __restrict__ b1,
    const float* __restrict__ W2, const float* __restrict__ b2,
    float* __restrict__ out, int n)
{
    extern __shared__ char smem[];
    ull*   Sd  = (ull*)smem;                 // {s,s} dup pairs, [BK][SSTR]
    ull*   Pd  = Sd + BK * SSTR;             // {p,p} dup pairs
    float* W1t = (float*)(Pd + BK * SSTR);   // [BK][WSTR], j-contiguous
    float* W2t = W1t + BK * WSTR;

    int tid = threadIdx.x;
    int tx = tid & 15, ty = tid >> 4;        // 16 x 16 thread grid
    int node0 = blockIdx.x * BM;
    int jbase = blockIdx.y * BN;

    ull acc1[32], acc2[32];                  // 8 m x 4 j-pairs, per matrix
    #pragma unroll
    for (int i = 0; i < 32; i++) { acc1[i] = 0ull; acc2[i] = 0ull; }

    int lrow = tid >> 2;    // 0..63
    int lq   = tid & 3;     // which float4 within a BK=16 row
    int kq   = lq * 4;

    for (int ck = 0; ck < D / BK; ck++) {
        int k0 = ck * BK;
        __syncthreads();
        // ---- load X tiles (ego & side -> s = e+s, p = e*s, duplicated pairs) ----
        #pragma unroll
        for (int r = 0; r < 2; r++) {
            int m = lrow + r * 64;
            int row = node0 + m; if (row >= n) row = n - 1;   // clamp (stores guarded)
            float4 e4 = *((const float4*)(ego    + (size_t)row * D + k0) + lq);
            float4 s4 = *((const float4*)(g_side + (size_t)row * D + k0) + lq);
            Sd[(kq+0)*SSTR + m] = pack2(e4.x + s4.x, e4.x + s4.x);
            Sd[(kq+1)*SSTR + m] = pack2(e4.y + s4.y, e4.y + s4.y);
            Sd[(kq+2)*SSTR + m] = pack2(e4.z + s4.z, e4.z + s4.z);
            Sd[(kq+3)*SSTR + m] = pack2(e4.w + s4.w, e4.w + s4.w);
            Pd[(kq+0)*SSTR + m] = pack2(e4.x * s4.x, e4.x * s4.x);
            Pd[(kq+1)*SSTR + m] = pack2(e4.y * s4.y, e4.y * s4.y);
            Pd[(kq+2)*SSTR + m] = pack2(e4.z * s4.z, e4.z * s4.z);
            Pd[(kq+3)*SSTR + m] = pack2(e4.w * s4.w, e4.w * s4.w);
            // ---- load W tiles transposed to [k][j] ----
            int j = lrow + r * 64;
            float4 w1v = *((const float4*)(W1 + (size_t)(jbase + j) * D + k0) + lq);
            float4 w2v = *((const float4*)(W2 + (size_t)(jbase + j) * D + k0) + lq);
            W1t[(kq+0)*WSTR + j] = w1v.x;  W1t[(kq+1)*WSTR + j] = w1v.y;
            W1t[(kq+2)*WSTR + j] = w1v.z;  W1t[(kq+3)*WSTR + j] = w1v.w;
            W2t[(kq+0)*WSTR + j] = w2v.x;  W2t[(kq+1)*WSTR + j] = w2v.y;
            W2t[(kq+2)*WSTR + j] = w2v.z;  W2t[(kq+3)*WSTR + j] = w2v.w;
        }
        __syncthreads();
        // ---- compute ----
        #pragma unroll
        for (int k = 0; k < BK; k++) {
            const ull* Sk = Sd + k * SSTR;
            const ull* Pk = Pd + k * SSTR;
            ull as[8], ap[8], w1r[4], w2r[4];
            #pragma unroll
            for (int i = 0; i < 4; i++) {
                as[i]   = Sk[ty*4 + i];
                as[4+i] = Sk[64 + ty*4 + i];
                ap[i]   = Pk[ty*4 + i];
                ap[4+i] = Pk[64 + ty*4 + i];
            }
            const float* Wk1 = W1t + k * WSTR;
            const float* Wk2 = W2t + k * WSTR;
            w1r[0] = *(const ull*)(Wk1 + 4*tx);
            w1r[1] = *(const ull*)(Wk1 + 4*tx + 2);
            w1r[2] = *(const ull*)(Wk1 + 64 + 4*tx);
            w1r[3] = *(const ull*)(Wk1 + 64 + 4*tx + 2);
            w2r[0] = *(const ull*)(Wk2 + 4*tx);
            w2r[1] = *(const ull*)(Wk2 + 4*tx + 2);
            w2r[2] = *(const ull*)(Wk2 + 64 + 4*tx);
            w2r[3] = *(const ull*)(Wk2 + 64 + 4*tx + 2);
            #pragma unroll
            for (int i = 0; i < 8; i++) {
                #pragma unroll
                for (int q = 0; q < 4; q++) {
                    ffma2(acc1[i*4 + q], as[i], w1r[q]);
                    ffma2(acc2[i*4 + q], ap[i], w2r[q]);
                }
            }
        }
    }

    // ---- epilogue: bias + leaky_relu + add, float4 stores ----
    float4 bv1[2], bv2[2];
    bv1[0] = *(const float4*)(b1 + jbase + 4*tx);
    bv1[1] = *(const float4*)(b1 + jbase + 64 + 4*tx);
    bv2[0] = *(const float4*)(b2 + jbase + 4*tx);
    bv2[1] = *(const float4*)(b2 + jbase + 64 + 4*tx);

    #pragma unroll
    for (int i = 0; i < 8; i++) {
        int m = (i < 4) ? (ty*4 + i) : (64 + ty*4 + (i - 4));
        int row = node0 + m;
        if (row < n) {
            #pragma unroll
            for (int g = 0; g < 2; g++) {
                float s0, s1, s2, s3, p0, p1, p2, p3;
                unpack2(acc1[i*4 + 2*g],     s0, s1);
                unpack2(acc1[i*4 + 2*g + 1], s2, s3);
                unpack2(acc2[i*4 + 2*g],     p0, p1);
                unpack2(acc2[i*4 + 2*g + 1], p2, p3);
                float4 bb1 = bv1[g], bb2 = bv2[g];
                float4 o;
                o.x = lrelu(s0 + bb1.x) + lrelu(p0 + bb2.x);
                o.y = lrelu(s1 + bb1.y) + lrelu(p1 + bb2.y);
                o.z = lrelu(s2 + bb1.z) + lrelu(p2 + bb2.z);
                o.w = lrelu(s3 + bb1.w) + lrelu(p3 + bb2.w);
                *(float4*)(out + (size_t)row * D + jbase + g*64 + 4*tx) = o;
            }
        }
    }
}

// ---------------- launch ----------------
extern "C" void kernel_launch(void* const* d_in, const int* in_sizes, int n_in,
                              void* d_out, int out_size) {
    const float* ego   = (const float*)d_in[0];
    const float* evals = (const float*)d_in[1];
    const float* W1    = (const float*)d_in[2];
    const float* b1    = (const float*)d_in[3];
    const float* W2    = (const float*)d_in[4];
    const float* b2    = (const float*)d_in[5];
    const int*   erows = (const int*)d_in[6];
    const int*   ecols = (const int*)d_in[7];
    float* out = (float*)d_out;

    int N = in_sizes[0] / D;
    int E = in_sizes[1];
    if (N > MAXN) N = MAXN;
    if (E > MAXE) E = MAXE;

    static bool attr_set = false;
    if (!attr_set) {
        cudaFuncSetAttribute(gemm_kernel, cudaFuncAttributeMaxDynamicSharedMemorySize, GEMM_SMEM);
        attr_set = true;
    }

    zero_hist_kernel<<<(N + 255) / 256, 256>>>(N);
    hist_kernel<<<(E + 255) / 256, 256>>>(erows, E);
    scan_kernel<<<1, 1024>>>(N);
    scatter_kernel<<<(E + 255) / 256, 256>>>(erows, ecols, evals, E);
    spmm_kernel<<<N, 64>>>((const float4*)ego);
    dim3 ggrid((N + BM - 1) / BM, D / BN);
    gemm_kernel<<<ggrid, 256, GEMM_SMEM>>>(ego, W1, b1, W2, b2, out, N);
}

// round 2
// speedup vs baseline: 1.5508x; 1.5508x over previous
#include <cuda_runtime.h>
#include <cuda_bf16.h>
#include <cstdint>

typedef unsigned long long ull;
typedef unsigned int uint;

#define MAXN 100000
#define MAXE 3200000
#define D 256

// ---------------- scratch ----------------
__device__ float g_side[(size_t)MAXN * D];   // SpMM result
__device__ float g_sval[MAXE];               // edge vals sorted by row
__device__ int   g_scol[MAXE];               // edge cols sorted by row
__device__ int   g_hist[MAXN];
__device__ int   g_off[MAXN + 1];
__device__ int   g_cur[MAXN];

__device__ __forceinline__ float lrelu(float x) { return x > 0.0f ? x : 0.01f * x; }
__device__ __forceinline__ uint f2tf32(float f) {
    uint u; asm("cvt.rna.tf32.f32 %0, %1;" : "=r"(u) : "f"(f)); return u;
}

// m16n8k8 tf32 mma, D += A*B
__device__ __forceinline__ void mma8(float* d, const uint* a, const uint* b) {
    asm volatile(
        "mma.sync.aligned.m16n8k8.row.col.f32.tf32.tf32.f32 "
        "{%0,%1,%2,%3}, {%4,%5,%6,%7}, {%8,%9}, {%0,%1,%2,%3};"
        : "+f"(d[0]), "+f"(d[1]), "+f"(d[2]), "+f"(d[3])
        : "r"(a[0]), "r"(a[1]), "r"(a[2]), "r"(a[3]), "r"(b[0]), "r"(b[1]));
}

// ---------------- 1. zero histogram ----------------
__global__ void zero_hist_kernel(int n) {
    int i = blockIdx.x * blockDim.x + threadIdx.x;
    if (i < n) g_hist[i] = 0;
}

// ---------------- 2. histogram of edge rows ----------------
__global__ void hist_kernel(const int* __restrict__ rows, int e) {
    int i = blockIdx.x * blockDim.x + threadIdx.x;
    if (i < e) atomicAdd(&g_hist[rows[i]], 1);
}

// ---------------- 3. exclusive scan (single block) ----------------
__global__ void scan_kernel(int n) {
    __shared__ int wsum[32];
    __shared__ int carry_s;
    int t = threadIdx.x, lane = t & 31, w = t >> 5;
    if (t == 0) { carry_s = 0; g_off[0] = 0; }
    __syncthreads();
    for (int base = 0; base < n; base += 1024) {
        int i = base + t;
        int v = (i < n) ? g_hist[i] : 0;
        int x = v;
        #pragma unroll
        for (int d2 = 1; d2 < 32; d2 <<= 1) {
            int y = __shfl_up_sync(0xffffffffu, x, d2);
            if (lane >= d2) x += y;
        }
        if (lane == 31) wsum[w] = x;
        __syncthreads();
        if (w == 0) {
            int s = wsum[lane];
            #pragma unroll
            for (int d2 = 1; d2 < 32; d2 <<= 1) {
                int y = __shfl_up_sync(0xffffffffu, s, d2);
                if (lane >= d2) s += y;
            }
            wsum[lane] = s;
        }
        __syncthreads();
        int incl = x + (w > 0 ? wsum[w - 1] : 0);
        int carry = carry_s;
        if (i < n) {
            g_off[i + 1] = carry + incl;
            g_cur[i]     = carry + incl - v;
        }
        int total = wsum[31];
        __syncthreads();
        if (t == 0) carry_s = carry + total;
        __syncthreads();
    }
}

// ---------------- 4. scatter edges to CSR order ----------------
__global__ void scatter_kernel(const int* __restrict__ rows, const int* __restrict__ cols,
                               const float* __restrict__ vals, int e) {
    int i = blockIdx.x * blockDim.x + threadIdx.x;
    if (i < e) {
        int r = rows[i];
        int p = atomicAdd(&g_cur[r], 1);
        g_scol[p] = cols[i];
        g_sval[p] = vals[i];
    }
}

// ---------------- 5. CSR SpMM: one block (64 threads) per node ----------------
__global__ __launch_bounds__(64) void spmm_kernel(const float4* __restrict__ ego4) {
    int node = blockIdx.x;
    int t = threadIdx.x;
    int beg = g_off[node], end = g_off[node + 1];
    float4 a0 = {0,0,0,0}, a1 = a0, a2 = a0, a3 = a0;
    int e = beg;
    for (; e + 4 <= end; e += 4) {
        int   c0 = g_scol[e],   c1 = g_scol[e+1], c2 = g_scol[e+2], c3 = g_scol[e+3];
        float v0 = g_sval[e],   v1 = g_sval[e+1], v2 = g_sval[e+2], v3 = g_sval[e+3];
        float4 x0 = ego4[(size_t)c0 * 64 + t];
        float4 x1 = ego4[(size_t)c1 * 64 + t];
        float4 x2 = ego4[(size_t)c2 * 64 + t];
        float4 x3 = ego4[(size_t)c3 * 64 + t];
        a0.x += v0*x0.x; a0.y += v0*x0.y; a0.z += v0*x0.z; a0.w += v0*x0.w;
        a1.x += v1*x1.x; a1.y += v1*x1.y; a1.z += v1*x1.z; a1.w += v1*x1.w;
        a2.x += v2*x2.x; a2.y += v2*x2.y; a2.z += v2*x2.z; a2.w += v2*x2.w;
        a3.x += v3*x3.x; a3.y += v3*x3.y; a3.z += v3*x3.z; a3.w += v3*x3.w;
    }
    for (; e < end; e++) {
        int c = g_scol[e]; float v = g_sval[e];
        float4 x = ego4[(size_t)c * 64 + t];
        a0.x += v*x.x; a0.y += v*x.y; a0.z += v*x.z; a0.w += v*x.w;
    }
    float4 r;
    r.x = (a0.x + a1.x) + (a2.x + a3.x);
    r.y = (a0.y + a1.y) + (a2.y + a3.y);
    r.z = (a0.z + a1.z) + (a2.z + a3.z);
    r.w = (a0.w + a1.w) + (a2.w + a3.w);
    ((float4*)g_side)[(size_t)node * 64 + t] = r;
}

// ---------------- 6. fused dual GEMM via tf32 tensor cores ----------------
// out[m][j] = lrelu( (ego+side)[m][:] . W1[j][:] + b1[j] )
//           + lrelu( (ego*side)[m][:] . W2[j][:] + b2[j] )
//
// Block tile 128(m) x 128(j), BK=32, 8 warps (2m x 4n), warp tile 64x32.
// Smem tiles row-major, stride 36 floats: frag LDS.32 loads hit banks 4g+c
// (all distinct -> conflict-free), producer STS.128 at the 4-cycle floor.
#define TBM 128
#define TBN 128
#define TBK 32
#define XSTR 36
#define TILE_F (TBM * XSTR)               // floats per tile
#define GEMM_SMEM (4 * TILE_F * 4)        // 4 tiles * 18432B = 73728B

__global__ __launch_bounds__(256, 1) void gemm_mma_kernel(
    const float* __restrict__ ego,
    const float* __restrict__ W1, const float* __restrict__ b1,
    const float* __restrict__ W2, const float* __restrict__ b2,
    float* __restrict__ out, int n)
{
    extern __shared__ char smem_raw[];
    uint* Xs  = (uint*)smem_raw;              // tf32 (ego+side) tile [128][36]
    uint* Xp  = Xs + TILE_F;                  // tf32 (ego*side)
    uint* W1t = Xp + TILE_F;                  // tf32 W1 rows [128][36]
    uint* W2t = W1t + TILE_F;

    const int tid  = threadIdx.x;
    const int lane = tid & 31;
    const int wid  = tid >> 5;
    const int wm   = (wid >> 2) * 64;         // warp m-offset in tile
    const int wn   = (wid & 3) * 32;          // warp n-offset in tile
    const int g    = lane >> 2;               // group id
    const int c    = lane & 3;                // thread-in-group

    const int node0 = blockIdx.x * TBM;
    const int jbase = blockIdx.y * TBN;

    // producer mapping: thread owns row (tid>>1), k-half (tid&1)
    const int pm   = tid >> 1;
    const int ph   = tid & 1;

    float acc1[4][4][4];   // [am][bn][reg]
    float acc2[4][4][4];
    #pragma unroll
    for (int i = 0; i < 4; i++)
        #pragma unroll
        for (int j = 0; j < 4; j++)
            #pragma unroll
            for (int r = 0; r < 4; r++) { acc1[i][j][r] = 0.f; acc2[i][j][r] = 0.f; }

    int xrow = node0 + pm; if (xrow >= n) xrow = n - 1;   // clamp (stores guarded)
    const float4* egoR  = (const float4*)(ego    + (size_t)xrow * D);
    const float4* sideR = (const float4*)(g_side + (size_t)xrow * D);
    const float4* w1R   = (const float4*)(W1 + (size_t)(jbase + pm) * D);
    const float4* w2R   = (const float4*)(W2 + (size_t)(jbase + pm) * D);

    for (int ck = 0; ck < D / TBK; ck++) {
        const int kq0 = ck * (TBK / 4);       // base float4 index within row
        __syncthreads();
        // ---- produce X tiles ----
        #pragma unroll
        for (int q = 0; q < 4; q++) {
            int f = ph * 4 + q;               // float4 index within BK (0..7)
            float4 e4 = egoR[kq0 + f];
            float4 s4 = sideR[kq0 + f];
            uint4 sv, pv;
            sv.x = f2tf32(e4.x + s4.x); sv.y = f2tf32(e4.y + s4.y);
            sv.z = f2tf32(e4.z + s4.z); sv.w = f2tf32(e4.w + s4.w);
            pv.x = f2tf32(e4.x * s4.x); pv.y = f2tf32(e4.y * s4.y);
            pv.z = f2tf32(e4.z * s4.z); pv.w = f2tf32(e4.w * s4.w);
            *(uint4*)(Xs + pm * XSTR + f * 4) = sv;
            *(uint4*)(Xp + pm * XSTR + f * 4) = pv;
        }
        // ---- produce W tiles ----
        #pragma unroll
        for (int q = 0; q < 4; q++) {
            int f = ph * 4 + q;
            float4 w1v = w1R[kq0 + f];
            float4 w2v = w2R[kq0 + f];
            uint4 a, b;
            a.x = f2tf32(w1v.x); a.y = f2tf32(w1v.y); a.z = f2tf32(w1v.z); a.w = f2tf32(w1v.w);
            b.x = f2tf32(w2v.x); b.y = f2tf32(w2v.y); b.z = f2tf32(w2v.z); b.w = f2tf32(w2v.w);
            *(uint4*)(W1t + pm * XSTR + f * 4) = a;
            *(uint4*)(W2t + pm * XSTR + f * 4) = b;
        }
        __syncthreads();
        // ---- consume: 4 k8-steps ----
        #pragma unroll
        for (int s = 0; s < 4; s++) {
            uint aS[4][4], aP[4][4];
            #pragma unroll
            for (int am = 0; am < 4; am++) {
                int base = (wm + am * 16 + g) * XSTR + s * 8 + c;
                aS[am][0] = Xs[base];
                aS[am][1] = Xs[base + 8 * XSTR];
                aS[am][2] = Xs[base + 4];
                aS[am][3] = Xs[base + 8 * XSTR + 4];
                aP[am][0] = Xp[base];
                aP[am][1] = Xp[base + 8 * XSTR];
                aP[am][2] = Xp[base + 4];
                aP[am][3] = Xp[base + 8 * XSTR + 4];
            }
            uint bW1[4][2], bW2[4][2];
            #pragma unroll
            for (int bn = 0; bn < 4; bn++) {
                int base = (wn + bn * 8 + g) * XSTR + s * 8 + c;
                bW1[bn][0] = W1t[base];
                bW1[bn][1] = W1t[base + 4];
                bW2[bn][0] = W2t[base];
                bW2[bn][1] = W2t[base + 4];
            }
            #pragma unroll
            for (int am = 0; am < 4; am++)
                #pragma unroll
                for (int bn = 0; bn < 4; bn++) {
                    mma8(acc1[am][bn], aS[am], bW1[bn]);
                    mma8(acc2[am][bn], aP[am], bW2[bn]);
                }
        }
    }

    // ---- epilogue: bias + leaky_relu + add ----
    #pragma unroll
    for (int bn = 0; bn < 4; bn++) {
        int col = jbase + wn + bn * 8 + c * 2;
        float2 bb1 = *(const float2*)(b1 + col);
        float2 bb2 = *(const float2*)(b2 + col);
        #pragma unroll
        for (int am = 0; am < 4; am++) {
            int r0 = node0 + wm + am * 16 + g;
            int r1 = r0 + 8;
            if (r0 < n) {
                float2 o;
                o.x = lrelu(acc1[am][bn][0] + bb1.x) + lrelu(acc2[am][bn][0] + bb2.x);
                o.y = lrelu(acc1[am][bn][1] + bb1.y) + lrelu(acc2[am][bn][1] + bb2.y);
                *(float2*)(out + (size_t)r0 * D + col) = o;
            }
            if (r1 < n) {
                float2 o;
                o.x = lrelu(acc1[am][bn][2] + bb1.x) + lrelu(acc2[am][bn][2] + bb2.x);
                o.y = lrelu(acc1[am][bn][3] + bb1.y) + lrelu(acc2[am][bn][3] + bb2.y);
                *(float2*)(out + (size_t)r1 * D + col) = o;
            }
        }
    }
}

// ---------------- launch ----------------
extern "C" void kernel_launch(void* const* d_in, const int* in_sizes, int n_in,
                              void* d_out, int out_size) {
    const float* ego   = (const float*)d_in[0];
    const float* evals = (const float*)d_in[1];
    const float* W1    = (const float*)d_in[2];
    const float* b1    = (const float*)d_in[3];
    const float* W2    = (const float*)d_in[4];
    const float* b2    = (const float*)d_in[5];
    const int*   erows = (const int*)d_in[6];
    const int*   ecols = (const int*)d_in[7];
    float* out = (float*)d_out;

    int N = in_sizes[0] / D;
    int E = in_sizes[1];
    if (N > MAXN) N = MAXN;
    if (E > MAXE) E = MAXE;

    static bool attr_set = false;
    if (!attr_set) {
        cudaFuncSetAttribute(gemm_mma_kernel, cudaFuncAttributeMaxDynamicSharedMemorySize, GEMM_SMEM);
        attr_set = true;
    }

    zero_hist_kernel<<<(N + 255) / 256, 256>>>(N);
    hist_kernel<<<(E + 255) / 256, 256>>>(erows, E);
    scan_kernel<<<1, 1024>>>(N);
    scatter_kernel<<<(E + 255) / 256, 256>>>(erows, ecols, evals, E);
    spmm_kernel<<<N, 64>>>((const float4*)ego);
    dim3 ggrid((N + TBM - 1) / TBM, TBN == D ? 1 : D / TBN);
    gemm_mma_kernel<<<ggrid, 256, GEMM_SMEM>>>(ego, W1, b1, W2, b2, out, N);
}

// round 7
// speedup vs baseline: 1.6947x; 1.0928x over previous
#include <cuda_runtime.h>
#include <cuda_bf16.h>
#include <cuda_fp16.h>
#include <cstdint>

typedef unsigned long long ull;
typedef unsigned int uint;

#define MAXN 100000
#define MAXE 3200000
#define D 256

// ---------------- scratch ----------------
__device__ float  g_side[(size_t)MAXN * D];     // SpMM result (fp32)
__device__ __half g_half[(size_t)MAXN * D];     // fp16 copy of ego for gathers
__device__ ull    g_epack[MAXE];                // packed {col, val} sorted by row
__device__ int    g_hist[MAXN];
__device__ int    g_off[MAXN + 1];
__device__ int    g_cur[MAXN];

__device__ __forceinline__ float lrelu(float x) { return x > 0.0f ? x : 0.01f * x; }
__device__ __forceinline__ uint f2tf32(float f) {
    uint u; asm("cvt.rna.tf32.f32 %0, %1;" : "=r"(u) : "f"(f)); return u;
}
__device__ __forceinline__ uint h2u(__half2 h) { return *reinterpret_cast<uint*>(&h); }
__device__ __forceinline__ __half2 u2h(uint u) { return *reinterpret_cast<__half2*>(&u); }

// m16n8k8 tf32 mma, D += A*B
__device__ __forceinline__ void mma8(float* d, const uint* a, const uint* b) {
    asm volatile(
        "mma.sync.aligned.m16n8k8.row.col.f32.tf32.tf32.f32 "
        "{%0,%1,%2,%3}, {%4,%5,%6,%7}, {%8,%9}, {%0,%1,%2,%3};"
        : "+f"(d[0]), "+f"(d[1]), "+f"(d[2]), "+f"(d[3])
        : "r"(a[0]), "r"(a[1]), "r"(a[2]), "r"(a[3]), "r"(b[0]), "r"(b[1]));
}

// ---------------- 0. fp32 -> fp16 gather table ----------------
__global__ void convert_kernel(const float4* __restrict__ ego4, int n4) {
    int i = blockIdx.x * blockDim.x + threadIdx.x;   // one float4 -> 2 half2
    if (i < n4) {
        float4 v = ego4[i];
        uint2 o;
        o.x = h2u(__floats2half2_rn(v.x, v.y));
        o.y = h2u(__floats2half2_rn(v.z, v.w));
        ((uint2*)g_half)[i] = o;
    }
}

// ---------------- 1. zero histogram ----------------
__global__ void zero_hist_kernel(int n) {
    int i = blockIdx.x * blockDim.x + threadIdx.x;
    if (i < n) g_hist[i] = 0;
}

// ---------------- 2. histogram of edge rows ----------------
__global__ void hist_kernel(const int* __restrict__ rows, int e) {
    int i = blockIdx.x * blockDim.x + threadIdx.x;
    if (i < e) atomicAdd(&g_hist[rows[i]], 1);
}

// ---------------- 3. exclusive scan (single block) ----------------
__global__ void scan_kernel(int n) {
    __shared__ int wsum[32];
    __shared__ int carry_s;
    int t = threadIdx.x, lane = t & 31, w = t >> 5;
    if (t == 0) { carry_s = 0; g_off[0] = 0; }
    __syncthreads();
    for (int base = 0; base < n; base += 1024) {
        int i = base + t;
        int v = (i < n) ? g_hist[i] : 0;
        int x = v;
        #pragma unroll
        for (int d2 = 1; d2 < 32; d2 <<= 1) {
            int y = __shfl_up_sync(0xffffffffu, x, d2);
            if (lane >= d2) x += y;
        }
        if (lane == 31) wsum[w] = x;
        __syncthreads();
        if (w == 0) {
            int s = wsum[lane];
            #pragma unroll
            for (int d2 = 1; d2 < 32; d2 <<= 1) {
                int y = __shfl_up_sync(0xffffffffu, s, d2);
                if (lane >= d2) s += y;
            }
            wsum[lane] = s;
        }
        __syncthreads();
        int incl = x + (w > 0 ? wsum[w - 1] : 0);
        int carry = carry_s;
        if (i < n) {
            g_off[i + 1] = carry + incl;
            g_cur[i]     = carry + incl - v;
        }
        int total = wsum[31];
        __syncthreads();
        if (t == 0) carry_s = carry + total;
        __syncthreads();
    }
}

// ---------------- 4. scatter edges (packed 8B records) ----------------
__global__ void scatter_kernel(const int* __restrict__ rows, const int* __restrict__ cols,
                               const float* __restrict__ vals, int e) {
    int i = blockIdx.x * blockDim.x + threadIdx.x;
    if (i < e) {
        int r = rows[i];
        ull rec = (ull)(uint)cols[i] | ((ull)__float_as_uint(vals[i]) << 32);
        int p = atomicAdd(&g_cur[r], 1);
        g_epack[p] = rec;
    }
}

// ---------------- 5. CSR SpMM over fp16 table: one 64-thr block per node ----
__global__ __launch_bounds__(64) void spmm_kernel() {
    int node = blockIdx.x;
    int t = threadIdx.x;                       // thread owns dims 4t..4t+3
    const uint2* tab = (const uint2*)g_half;   // [N][64] uint2 (4 halves each)
    int beg = g_off[node], end = g_off[node + 1];
    float4 a0 = {0,0,0,0}, a1 = a0, a2 = a0, a3 = a0;
    int e = beg;
    for (; e + 4 <= end; e += 4) {
        ull r0 = g_epack[e],   r1 = g_epack[e+1];
        ull r2 = g_epack[e+2], r3 = g_epack[e+3];
        uint  c0 = (uint)r0, c1 = (uint)r1, c2 = (uint)r2, c3 = (uint)r3;
        float v0 = __uint_as_float((uint)(r0 >> 32));
        float v1 = __uint_as_float((uint)(r1 >> 32));
        float v2 = __uint_as_float((uint)(r2 >> 32));
        float v3 = __uint_as_float((uint)(r3 >> 32));
        uint2 x0 = tab[(size_t)c0 * 64 + t];
        uint2 x1 = tab[(size_t)c1 * 64 + t];
        uint2 x2 = tab[(size_t)c2 * 64 + t];
        uint2 x3 = tab[(size_t)c3 * 64 + t];
        float2 p, q;
        p = __half22float2(u2h(x0.x)); q = __half22float2(u2h(x0.y));
        a0.x += v0*p.x; a0.y += v0*p.y; a0.z += v0*q.x; a0.w += v0*q.y;
        p = __half22float2(u2h(x1.x)); q = __half22float2(u2h(x1.y));
        a1.x += v1*p.x; a1.y += v1*p.y; a1.z += v1*q.x; a1.w += v1*q.y;
        p = __half22float2(u2h(x2.x)); q = __half22float2(u2h(x2.y));
        a2.x += v2*p.x; a2.y += v2*p.y; a2.z += v2*q.x; a2.w += v2*q.y;
        p = __half22float2(u2h(x3.x)); q = __half22float2(u2h(x3.y));
        a3.x += v3*p.x; a3.y += v3*p.y; a3.z += v3*q.x; a3.w += v3*q.y;
    }
    for (; e < end; e++) {
        ull r0 = g_epack[e];
        uint c = (uint)r0;
        float v = __uint_as_float((uint)(r0 >> 32));
        uint2 x = tab[(size_t)c * 64 + t];
        float2 p = __half22float2(u2h(x.x));
        float2 q = __half22float2(u2h(x.y));
        a0.x += v*p.x; a0.y += v*p.y; a0.z += v*q.x; a0.w += v*q.y;
    }
    float4 r;
    r.x = (a0.x + a1.x) + (a2.x + a3.x);
    r.y = (a0.y + a1.y) + (a2.y + a3.y);
    r.z = (a0.z + a1.z) + (a2.z + a3.z);
    r.w = (a0.w + a1.w) + (a2.w + a3.w);
    ((float4*)g_side)[(size_t)node * 64 + t] = r;
}

// ---------------- 6. fused dual GEMM via tf32 tensor cores ----------------
#define TBM 128
#define TBN 128
#define TBK 32
#define XSTR 36
#define TILE_F (TBM * XSTR)
#define GEMM_SMEM (4 * TILE_F * 4)        // 73728B

__global__ __launch_bounds__(256, 1) void gemm_mma_kernel(
    const float* __restrict__ ego,
    const float* __restrict__ W1, const float* __restrict__ b1,
    const float* __restrict__ W2, const float* __restrict__ b2,
    float* __restrict__ out, int n)
{
    extern __shared__ char smem_raw[];
    uint* Xs  = (uint*)smem_raw;
    uint* Xp  = Xs + TILE_F;
    uint* W1t = Xp + TILE_F;
    uint* W2t = W1t + TILE_F;

    const int tid  = threadIdx.x;
    const int lane = tid & 31;
    const int wid  = tid >> 5;
    const int wm   = (wid >> 2) * 64;
    const int wn   = (wid & 3) * 32;
    const int g    = lane >> 2;
    const int c    = lane & 3;

    const int node0 = blockIdx.x * TBM;
    const int jbase = blockIdx.y * TBN;

    const int pm   = tid >> 1;
    const int ph   = tid & 1;

    float acc1[4][4][4];
    float acc2[4][4][4];
    #pragma unroll
    for (int i = 0; i < 4; i++)
        #pragma unroll
        for (int j = 0; j < 4; j++)
            #pragma unroll
            for (int r = 0; r < 4; r++) { acc1[i][j][r] = 0.f; acc2[i][j][r] = 0.f; }

    int xrow = node0 + pm; if (xrow >= n) xrow = n - 1;
    const float4* egoR  = (const float4*)(ego    + (size_t)xrow * D);
    const float4* sideR = (const float4*)(g_side + (size_t)xrow * D);
    const float4* w1R   = (const float4*)(W1 + (size_t)(jbase + pm) * D);
    const float4* w2R   = (const float4*)(W2 + (size_t)(jbase + pm) * D);

    for (int ck = 0; ck < D / TBK; ck++) {
        const int kq0 = ck * (TBK / 4);
        __syncthreads();
        #pragma unroll
        for (int q = 0; q < 4; q++) {
            int f = ph * 4 + q;
            float4 e4 = egoR[kq0 + f];
            float4 s4 = sideR[kq0 + f];
            uint4 sv, pv;
            sv.x = f2tf32(e4.x + s4.x); sv.y = f2tf32(e4.y + s4.y);
            sv.z = f2tf32(e4.z + s4.z); sv.w = f2tf32(e4.w + s4.w);
            pv.x = f2tf32(e4.x * s4.x); pv.y = f2tf32(e4.y * s4.y);
            pv.z = f2tf32(e4.z * s4.z); pv.w = f2tf32(e4.w * s4.w);
            *(uint4*)(Xs + pm * XSTR + f * 4) = sv;
            *(uint4*)(Xp + pm * XSTR + f * 4) = pv;
        }
        #pragma unroll
        for (int q = 0; q < 4; q++) {
            int f = ph * 4 + q;
            float4 w1v = w1R[kq0 + f];
            float4 w2v = w2R[kq0 + f];
            uint4 a, b;
            a.x = f2tf32(w1v.x); a.y = f2tf32(w1v.y); a.z = f2tf32(w1v.z); a.w = f2tf32(w1v.w);
            b.x = f2tf32(w2v.x); b.y = f2tf32(w2v.y); b.z = f2tf32(w2v.z); b.w = f2tf32(w2v.w);
            *(uint4*)(W1t + pm * XSTR + f * 4) = a;
            *(uint4*)(W2t + pm * XSTR + f * 4) = b;
        }
        __syncthreads();
        #pragma unroll
        for (int s = 0; s < 4; s++) {
            uint aS[4][4], aP[4][4];
            #pragma unroll
            for (int am = 0; am < 4; am++) {
                int base = (wm + am * 16 + g) * XSTR + s * 8 + c;
                aS[am][0] = Xs[base];
                aS[am][1] = Xs[base + 8 * XSTR];
                aS[am][2] = Xs[base + 4];
                aS[am][3] = Xs[base + 8 * XSTR + 4];
                aP[am][0] = Xp[base];
                aP[am][1] = Xp[base + 8 * XSTR];
                aP[am][2] = Xp[base + 4];
                aP[am][3] = Xp[base + 8 * XSTR + 4];
            }
            uint bW1[4][2], bW2[4][2];
            #pragma unroll
            for (int bn = 0; bn < 4; bn++) {
                int base = (wn + bn * 8 + g) * XSTR + s * 8 + c;
                bW1[bn][0] = W1t[base];
                bW1[bn][1] = W1t[base + 4];
                bW2[bn][0] = W2t[base];
                bW2[bn][1] = W2t[base + 4];
            }
            #pragma unroll
            for (int am = 0; am < 4; am++)
                #pragma unroll
                for (int bn = 0; bn < 4; bn++) {
                    mma8(acc1[am][bn], aS[am], bW1[bn]);
                    mma8(acc2[am][bn], aP[am], bW2[bn]);
                }
        }
    }

    #pragma unroll
    for (int bn = 0; bn < 4; bn++) {
        int col = jbase + wn + bn * 8 + c * 2;
        float2 bb1 = *(const float2*)(b1 + col);
        float2 bb2 = *(const float2*)(b2 + col);
        #pragma unroll
        for (int am = 0; am < 4; am++) {
            int r0 = node0 + wm + am * 16 + g;
            int r1 = r0 + 8;
            if (r0 < n) {
                float2 o;
                o.x = lrelu(acc1[am][bn][0] + bb1.x) + lrelu(acc2[am][bn][0] + bb2.x);
                o.y = lrelu(acc1[am][bn][1] + bb1.y) + lrelu(acc2[am][bn][1] + bb2.y);
                *(float2*)(out + (size_t)r0 * D + col) = o;
            }
            if (r1 < n) {
                float2 o;
                o.x = lrelu(acc1[am][bn][2] + bb1.x) + lrelu(acc2[am][bn][2] + bb2.x);
                o.y = lrelu(acc1[am][bn][3] + bb1.y) + lrelu(acc2[am][bn][3] + bb2.y);
                *(float2*)(out + (size_t)r1 * D + col) = o;
            }
        }
    }
}

// ---------------- launch ----------------
extern "C" void kernel_launch(void* const* d_in, const int* in_sizes, int n_in,
                              void* d_out, int out_size) {
    const float* ego   = (const float*)d_in[0];
    const float* evals = (const float*)d_in[1];
    const float* W1    = (const float*)d_in[2];
    const float* b1    = (const float*)d_in[3];
    const float* W2    = (const float*)d_in[4];
    const float* b2    = (const float*)d_in[5];
    const int*   erows = (const int*)d_in[6];
    const int*   ecols = (const int*)d_in[7];
    float* out = (float*)d_out;

    int N = in_sizes[0] / D;
    int E = in_sizes[1];
    if (N > MAXN) N = MAXN;
    if (E > MAXE) E = MAXE;

    static bool attr_set = false;
    if (!attr_set) {
        cudaFuncSetAttribute(gemm_mma_kernel, cudaFuncAttributeMaxDynamicSharedMemorySize, GEMM_SMEM);
        attr_set = true;
    }

    int n4 = N * (D / 4);
    convert_kernel<<<(n4 + 255) / 256, 256>>>((const float4*)ego, n4);
    zero_hist_kernel<<<(N + 255) / 256, 256>>>(N);
    hist_kernel<<<(E + 255) / 256, 256>>>(erows, E);
    scan_kernel<<<1, 1024>>>(N);
    scatter_kernel<<<(E + 255) / 256, 256>>>(erows, ecols, evals, E);
    spmm_kernel<<<N, 64>>>();
    dim3 ggrid((N + TBM - 1) / TBM, TBN == D ? 1 : D / TBN);
    gemm_mma_kernel<<<ggrid, 256, GEMM_SMEM>>>(ego, W1, b1, W2, b2, out, N);
}

// round 8
// speedup vs baseline: 1.8802x; 1.1095x over previous
#include <cuda_runtime.h>
#include <cuda_bf16.h>
#include <cuda_fp16.h>
#include <cstdint>

typedef unsigned long long ull;
typedef unsigned int uint;

#define MAXN 100000
#define MAXE 3200000
#define D 256
#define SBLK 1024
#define MAXPART 128        // ceil(MAXN/SBLK) = 98

// ---------------- scratch ----------------
__device__ float  g_side[(size_t)MAXN * D];     // SpMM result (fp32)
__device__ __half g_half[(size_t)MAXN * D];     // fp16 copy of ego for gathers
__device__ ull    g_epack[MAXE];                // packed {col, val} sorted by row
__device__ int    g_hist[MAXN];
__device__ int    g_off[MAXN + 1];
__device__ int    g_cur[MAXN];
__device__ int    g_part[MAXPART];

__device__ __forceinline__ float lrelu(float x) { return x > 0.0f ? x : 0.01f * x; }
__device__ __forceinline__ uint f2tf32(float f) {
    uint u; asm("cvt.rna.tf32.f32 %0, %1;" : "=r"(u) : "f"(f)); return u;
}
__device__ __forceinline__ uint h2u(__half2 h) { return *reinterpret_cast<uint*>(&h); }
__device__ __forceinline__ __half2 u2h(uint u) { return *reinterpret_cast<__half2*>(&u); }

// m16n8k8 tf32 mma, D += A*B
__device__ __forceinline__ void mma8(float* d, const uint* a, const uint* b) {
    asm volatile(
        "mma.sync.aligned.m16n8k8.row.col.f32.tf32.tf32.f32 "
        "{%0,%1,%2,%3}, {%4,%5,%6,%7}, {%8,%9}, {%0,%1,%2,%3};"
        : "+f"(d[0]), "+f"(d[1]), "+f"(d[2]), "+f"(d[3])
        : "r"(a[0]), "r"(a[1]), "r"(a[2]), "r"(a[3]), "r"(b[0]), "r"(b[1]));
}

// ---------------- 0. fp32 -> fp16 gather table ----------------
__global__ void convert_kernel(const float4* __restrict__ ego4, int n4) {
    int i = blockIdx.x * blockDim.x + threadIdx.x;
    if (i < n4) {
        float4 v = ego4[i];
        uint2 o;
        o.x = h2u(__floats2half2_rn(v.x, v.y));
        o.y = h2u(__floats2half2_rn(v.z, v.w));
        ((uint2*)g_half)[i] = o;
    }
}

// ---------------- 1. zero histogram ----------------
__global__ void zero_hist_kernel(int n) {
    int i = blockIdx.x * blockDim.x + threadIdx.x;
    if (i < n) g_hist[i] = 0;
}

// ---------------- 2. histogram of edge rows ----------------
__global__ void hist_kernel(const int* __restrict__ rows, int e) {
    int i = blockIdx.x * blockDim.x + threadIdx.x;
    if (i < e) atomicAdd(&g_hist[rows[i]], 1);
}

// ---------------- 3a. per-block reduce of hist ----------------
__global__ __launch_bounds__(SBLK) void scan_reduce_kernel(int n) {
    __shared__ int ws[32];
    int tid = threadIdx.x, lane = tid & 31, w = tid >> 5;
    int i = blockIdx.x * SBLK + tid;
    int x = (i < n) ? g_hist[i] : 0;
    #pragma unroll
    for (int d = 16; d; d >>= 1) x += __shfl_down_sync(0xffffffffu, x, d);
    if (lane == 0) ws[w] = x;
    __syncthreads();
    if (w == 0) {
        int s = ws[lane];
        #pragma unroll
        for (int d = 16; d; d >>= 1) s += __shfl_down_sync(0xffffffffu, s, d);
        if (lane == 0) g_part[blockIdx.x] = s;
    }
}

// ---------------- 3b. exclusive scan of partials (1 small block) --------
__global__ void scan_part_kernel(int nb) {
    __shared__ int wsum[4];
    int t = threadIdx.x, lane = t & 31, w = t >> 5;
    int v = (t < nb) ? g_part[t] : 0;
    int x = v;
    #pragma unroll
    for (int d = 1; d < 32; d <<= 1) {
        int y = __shfl_up_sync(0xffffffffu, x, d);
        if (lane >= d) x += y;
    }
    if (lane == 31) wsum[w] = x;
    __syncthreads();
    if (t == 0) {
        int a = 0;
        #pragma unroll
        for (int k = 0; k < 4; k++) { int b = wsum[k]; wsum[k] = a; a += b; }
    }
    __syncthreads();
    if (t < nb) g_part[t] = x + wsum[w] - v;     // exclusive prefix
    if (t == 0) g_off[0] = 0;
}

// ---------------- 3c. final block scans with base offset ----------------
__global__ __launch_bounds__(SBLK) void scan_final_kernel(int n) {
    __shared__ int ws[32];
    int tid = threadIdx.x, lane = tid & 31, w = tid >> 5;
    int i = blockIdx.x * SBLK + tid;
    int v = (i < n) ? g_hist[i] : 0;
    int x = v;
    #pragma unroll
    for (int d = 1; d < 32; d <<= 1) {
        int y = __shfl_up_sync(0xffffffffu, x, d);
        if (lane >= d) x += y;
    }
    if (lane == 31) ws[w] = x;
    __syncthreads();
    if (w == 0) {
        int s = ws[lane];
        #pragma unroll
        for (int d = 1; d < 32; d <<= 1) {
            int y = __shfl_up_sync(0xffffffffu, s, d);
            if (lane >= d) s += y;
        }
        ws[lane] = s;
    }
    __syncthreads();
    int incl = x + g_part[blockIdx.x] + (w > 0 ? ws[w - 1] : 0);
    if (i < n) {
        g_off[i + 1] = incl;
        g_cur[i]     = incl - v;
    }
}

// ---------------- 4. scatter edges (packed 8B records) ----------------
__global__ void scatter_kernel(const int* __restrict__ rows, const int* __restrict__ cols,
                               const float* __restrict__ vals, int e) {
    int i = blockIdx.x * blockDim.x + threadIdx.x;
    if (i < e) {
        int r = rows[i];
        ull rec = (ull)(uint)cols[i] | ((ull)__float_as_uint(vals[i]) << 32);
        int p = atomicAdd(&g_cur[r], 1);
        g_epack[p] = rec;
    }
}

// ---------------- 5. CSR SpMM over fp16 table: one 64-thr block per node ----
__global__ __launch_bounds__(64) void spmm_kernel() {
    int node = blockIdx.x;
    int t = threadIdx.x;
    const uint2* tab = (const uint2*)g_half;
    int beg = g_off[node], end = g_off[node + 1];
    float4 a0 = {0,0,0,0}, a1 = a0, a2 = a0, a3 = a0;
    int e = beg;
    for (; e + 4 <= end; e += 4) {
        ull r0 = g_epack[e],   r1 = g_epack[e+1];
        ull r2 = g_epack[e+2], r3 = g_epack[e+3];
        uint  c0 = (uint)r0, c1 = (uint)r1, c2 = (uint)r2, c3 = (uint)r3;
        float v0 = __uint_as_float((uint)(r0 >> 32));
        float v1 = __uint_as_float((uint)(r1 >> 32));
        float v2 = __uint_as_float((uint)(r2 >> 32));
        float v3 = __uint_as_float((uint)(r3 >> 32));
        uint2 x0 = tab[(size_t)c0 * 64 + t];
        uint2 x1 = tab[(size_t)c1 * 64 + t];
        uint2 x2 = tab[(size_t)c2 * 64 + t];
        uint2 x3 = tab[(size_t)c3 * 64 + t];
        float2 p, q;
        p = __half22float2(u2h(x0.x)); q = __half22float2(u2h(x0.y));
        a0.x += v0*p.x; a0.y += v0*p.y; a0.z += v0*q.x; a0.w += v0*q.y;
        p = __half22float2(u2h(x1.x)); q = __half22float2(u2h(x1.y));
        a1.x += v1*p.x; a1.y += v1*p.y; a1.z += v1*q.x; a1.w += v1*q.y;
        p = __half22float2(u2h(x2.x)); q = __half22float2(u2h(x2.y));
        a2.x += v2*p.x; a2.y += v2*p.y; a2.z += v2*q.x; a2.w += v2*q.y;
        p = __half22float2(u2h(x3.x)); q = __half22float2(u2h(x3.y));
        a3.x += v3*p.x; a3.y += v3*p.y; a3.z += v3*q.x; a3.w += v3*q.y;
    }
    for (; e < end; e++) {
        ull r0 = g_epack[e];
        uint c = (uint)r0;
        float v = __uint_as_float((uint)(r0 >> 32));
        uint2 x = tab[(size_t)c * 64 + t];
        float2 p = __half22float2(u2h(x.x));
        float2 q = __half22float2(u2h(x.y));
        a0.x += v*p.x; a0.y += v*p.y; a0.z += v*q.x; a0.w += v*q.y;
    }
    float4 r;
    r.x = (a0.x + a1.x) + (a2.x + a3.x);
    r.y = (a0.y + a1.y) + (a2.y + a3.y);
    r.z = (a0.z + a1.z) + (a2.z + a3.z);
    r.w = (a0.w + a1.w) + (a2.w + a3.w);
    ((float4*)g_side)[(size_t)node * 64 + t] = r;
}

// ---------------- 6. fused dual GEMM via tf32 tensor cores ----------------
#define TBM 128
#define TBN 128
#define TBK 32
#define XSTR 36
#define TILE_F (TBM * XSTR)
#define GEMM_SMEM (4 * TILE_F * 4)        // 73728B

__global__ __launch_bounds__(256, 1) void gemm_mma_kernel(
    const float* __restrict__ ego,
    const float* __restrict__ W1, const float* __restrict__ b1,
    const float* __restrict__ W2, const float* __restrict__ b2,
    float* __restrict__ out, int n)
{
    extern __shared__ char smem_raw[];
    uint* Xs  = (uint*)smem_raw;
    uint* Xp  = Xs + TILE_F;
    uint* W1t = Xp + TILE_F;
    uint* W2t = W1t + TILE_F;

    const int tid  = threadIdx.x;
    const int lane = tid & 31;
    const int wid  = tid >> 5;
    const int wm   = (wid >> 2) * 64;
    const int wn   = (wid & 3) * 32;
    const int g    = lane >> 2;
    const int c    = lane & 3;

    const int node0 = blockIdx.x * TBM;
    const int jbase = blockIdx.y * TBN;

    const int pm   = tid >> 1;
    const int ph   = tid & 1;

    float acc1[4][4][4];
    float acc2[4][4][4];
    #pragma unroll
    for (int i = 0; i < 4; i++)
        #pragma unroll
        for (int j = 0; j < 4; j++)
            #pragma unroll
            for (int r = 0; r < 4; r++) { acc1[i][j][r] = 0.f; acc2[i][j][r] = 0.f; }

    int xrow = node0 + pm; if (xrow >= n) xrow = n - 1;
    const float4* egoR  = (const float4*)(ego    + (size_t)xrow * D);
    const float4* sideR = (const float4*)(g_side + (size_t)xrow * D);
    const float4* w1R   = (const float4*)(W1 + (size_t)(jbase + pm) * D);
    const float4* w2R   = (const float4*)(W2 + (size_t)(jbase + pm) * D);

    for (int ck = 0; ck < D / TBK; ck++) {
        const int kq0 = ck * (TBK / 4);
        __syncthreads();
        #pragma unroll
        for (int q = 0; q < 4; q++) {
            int f = ph * 4 + q;
            float4 e4 = egoR[kq0 + f];
            float4 s4 = sideR[kq0 + f];
            uint4 sv, pv;
            sv.x = f2tf32(e4.x + s4.x); sv.y = f2tf32(e4.y + s4.y);
            sv.z = f2tf32(e4.z + s4.z); sv.w = f2tf32(e4.w + s4.w);
            pv.x = f2tf32(e4.x * s4.x); pv.y = f2tf32(e4.y * s4.y);
            pv.z = f2tf32(e4.z * s4.z); pv.w = f2tf32(e4.w * s4.w);
            *(uint4*)(Xs + pm * XSTR + f * 4) = sv;
            *(uint4*)(Xp + pm * XSTR + f * 4) = pv;
        }
        #pragma unroll
        for (int q = 0; q < 4; q++) {
            int f = ph * 4 + q;
            float4 w1v = w1R[kq0 + f];
            float4 w2v = w2R[kq0 + f];
            uint4 a, b;
            a.x = f2tf32(w1v.x); a.y = f2tf32(w1v.y); a.z = f2tf32(w1v.z); a.w = f2tf32(w1v.w);
            b.x = f2tf32(w2v.x); b.y = f2tf32(w2v.y); b.z = f2tf32(w2v.z); b.w = f2tf32(w2v.w);
            *(uint4*)(W1t + pm * XSTR + f * 4) = a;
            *(uint4*)(W2t + pm * XSTR + f * 4) = b;
        }
        __syncthreads();
        #pragma unroll
        for (int s = 0; s < 4; s++) {
            uint aS[4][4], aP[4][4];
            #pragma unroll
            for (int am = 0; am < 4; am++) {
                int base = (wm + am * 16 + g) * XSTR + s * 8 + c;
                aS[am][0] = Xs[base];
                aS[am][1] = Xs[base + 8 * XSTR];
                aS[am][2] = Xs[base + 4];
                aS[am][3] = Xs[base + 8 * XSTR + 4];
                aP[am][0] = Xp[base];
                aP[am][1] = Xp[base + 8 * XSTR];
                aP[am][2] = Xp[base + 4];
                aP[am][3] = Xp[base + 8 * XSTR + 4];
            }
            uint bW1[4][2], bW2[4][2];
            #pragma unroll
            for (int bn = 0; bn < 4; bn++) {
                int base = (wn + bn * 8 + g) * XSTR + s * 8 + c;
                bW1[bn][0] = W1t[base];
                bW1[bn][1] = W1t[base + 4];
                bW2[bn][0] = W2t[base];
                bW2[bn][1] = W2t[base + 4];
            }
            #pragma unroll
            for (int am = 0; am < 4; am++)
                #pragma unroll
                for (int bn = 0; bn < 4; bn++) {
                    mma8(acc1[am][bn], aS[am], bW1[bn]);
                    mma8(acc2[am][bn], aP[am], bW2[bn]);
                }
        }
    }

    #pragma unroll
    for (int bn = 0; bn < 4; bn++) {
        int col = jbase + wn + bn * 8 + c * 2;
        float2 bb1 = *(const float2*)(b1 + col);
        float2 bb2 = *(const float2*)(b2 + col);
        #pragma unroll
        for (int am = 0; am < 4; am++) {
            int r0 = node0 + wm + am * 16 + g;
            int r1 = r0 + 8;
            if (r0 < n) {
                float2 o;
                o.x = lrelu(acc1[am][bn][0] + bb1.x) + lrelu(acc2[am][bn][0] + bb2.x);
                o.y = lrelu(acc1[am][bn][1] + bb1.y) + lrelu(acc2[am][bn][1] + bb2.y);
                *(float2*)(out + (size_t)r0 * D + col) = o;
            }
            if (r1 < n) {
                float2 o;
                o.x = lrelu(acc1[am][bn][2] + bb1.x) + lrelu(acc2[am][bn][2] + bb2.x);
                o.y = lrelu(acc1[am][bn][3] + bb1.y) + lrelu(acc2[am][bn][3] + bb2.y);
                *(float2*)(out + (size_t)r1 * D + col) = o;
            }
        }
    }
}

// ---------------- launch ----------------
extern "C" void kernel_launch(void* const* d_in, const int* in_sizes, int n_in,
                              void* d_out, int out_size) {
    const float* ego   = (const float*)d_in[0];
    const float* evals = (const float*)d_in[1];
    const float* W1    = (const float*)d_in[2];
    const float* b1    = (const float*)d_in[3];
    const float* W2    = (const float*)d_in[4];
    const float* b2    = (const float*)d_in[5];
    const int*   erows = (const int*)d_in[6];
    const int*   ecols = (const int*)d_in[7];
    float* out = (float*)d_out;

    int N = in_sizes[0] / D;
    int E = in_sizes[1];
    if (N > MAXN) N = MAXN;
    if (E > MAXE) E = MAXE;

    static bool attr_set = false;
    if (!attr_set) {
        cudaFuncSetAttribute(gemm_mma_kernel, cudaFuncAttributeMaxDynamicSharedMemorySize, GEMM_SMEM);
        attr_set = true;
    }

    int n4 = N * (D / 4);
    int nscan = (N + SBLK - 1) / SBLK;
    convert_kernel<<<(n4 + 255) / 256, 256>>>((const float4*)ego, n4);
    zero_hist_kernel<<<(N + 255) / 256, 256>>>(N);
    hist_kernel<<<(E + 255) / 256, 256>>>(erows, E);
    scan_reduce_kernel<<<nscan, SBLK>>>(N);
    scan_part_kernel<<<1, 128>>>(nscan);
    scan_final_kernel<<<nscan, SBLK>>>(N);
    scatter_kernel<<<(E + 255) / 256, 256>>>(erows, ecols, evals, E);
    spmm_kernel<<<N, 64>>>();
    dim3 ggrid((N + TBM - 1) / TBM, TBN == D ? 1 : D / TBN);
    gemm_mma_kernel<<<ggrid, 256, GEMM_SMEM>>>(ego, W1, b1, W2, b2, out, N);
}